// round 6
// baseline (speedup 1.0000x reference)
#include <cuda_runtime.h>
#include <cuda_bf16.h>
#include <cstdint>

// Problem dims
#define Bdim 4
#define Mdim 256
#define Ndim 128
#define Ddim 512
#define Cdim 1024
#define ROWS (Bdim*Mdim*Ndim)   // 131072

// -------- scratch (device globals) --------
__device__ float g_he[Bdim*Mdim*Ddim];          // 2 MB
__device__ float g_hd[Bdim*Ndim*Ddim];          // 1 MB
__device__ __nv_bfloat16 g_w2b[Cdim*Ddim];      // 1 MB   w2 -> bf16
__device__ __nv_bfloat16 g_H[(size_t)ROWS*Ddim];// 134 MB H = tanh(...) bf16
__device__ float g_part[(size_t)ROWS*64];       // 33.5MB (max,sum) x32 per row
__device__ float g_lse[ROWS];                   // 0.5 MB

// -------- helpers --------
__device__ __forceinline__ float tanh_fast(float x){
    float r; asm("tanh.approx.f32 %0, %1;" : "=f"(r) : "f"(x)); return r;
}
__device__ __forceinline__ unsigned pk(float lo, float hi){
    unsigned r;
    asm("cvt.rn.bf16x2.f32 %0, %2, %1;" : "=r"(r) : "f"(lo), "f"(hi));
    return r;
}
__device__ __forceinline__ void mma_bf16(float* d, const unsigned* a, const unsigned* b){
    asm volatile(
        "mma.sync.aligned.m16n8k16.row.col.f32.bf16.bf16.f32 "
        "{%0,%1,%2,%3}, {%4,%5,%6,%7}, {%8,%9}, {%0,%1,%2,%3};\n"
        : "+f"(d[0]), "+f"(d[1]), "+f"(d[2]), "+f"(d[3])
        : "r"(a[0]), "r"(a[1]), "r"(a[2]), "r"(a[3]), "r"(b[0]), "r"(b[1]));
}

// ================= K0: w2 -> bf16 =================
__global__ __launch_bounds__(256) void cvtw2b_k(const float* __restrict__ w2){
    const int i = blockIdx.x*256 + threadIdx.x;
    float4 v0 = ((const float4*)w2)[2*i];
    float4 v1 = ((const float4*)w2)[2*i + 1];
    uint4 o;
    o.x = pk(v0.x, v0.y); o.y = pk(v0.z, v0.w);
    o.z = pk(v1.x, v1.y); o.w = pk(v1.z, v1.w);
    ((uint4*)g_w2b)[i] = o;
}

// ================= K1: fc1 small GEMMs (fp32, exact) =================
__global__ __launch_bounds__(256) void fc1_k(const float* __restrict__ X,
                                             const float* __restrict__ W,
                                             int woff, int which){
    __shared__ float sX[16][64];
    __shared__ float sW[16][64];
    float* __restrict__ Y = which ? g_hd : g_he;
    const int t  = threadIdx.x;
    const int tx = t & 15, ty = t >> 4;
    const int rb = blockIdx.y << 6, eb = blockIdx.x << 6;
    const int r  = t >> 2, kq = (t & 3) << 2;

    float acc[4][4];
#pragma unroll
    for (int i = 0; i < 4; i++)
#pragma unroll
        for (int j = 0; j < 4; j++) acc[i][j] = 0.f;

    for (int k0 = 0; k0 < Ddim; k0 += 16){
        float4 xv = *(const float4*)(X + (rb + r)*Ddim + k0 + kq);
        float4 wv = *(const float4*)(W + (eb + r)*(2*Ddim) + woff + k0 + kq);
        __syncthreads();
        sX[kq+0][r] = xv.x; sX[kq+1][r] = xv.y; sX[kq+2][r] = xv.z; sX[kq+3][r] = xv.w;
        sW[kq+0][r] = wv.x; sW[kq+1][r] = wv.y; sW[kq+2][r] = wv.z; sW[kq+3][r] = wv.w;
        __syncthreads();
#pragma unroll
        for (int k = 0; k < 16; k++){
            float4 a  = *(const float4*)&sX[k][ty << 2];
            float4 bv = *(const float4*)&sW[k][tx << 2];
            float av[4] = {a.x, a.y, a.z, a.w};
            float bb[4] = {bv.x, bv.y, bv.z, bv.w};
#pragma unroll
            for (int i = 0; i < 4; i++)
#pragma unroll
                for (int j = 0; j < 4; j++) acc[i][j] = fmaf(av[i], bb[j], acc[i][j]);
        }
    }
#pragma unroll
    for (int i = 0; i < 4; i++)
#pragma unroll
        for (int j = 0; j < 4; j++)
            Y[(rb + (ty<<2) + i)*Ddim + eb + (tx<<2) + j] = acc[i][j];
}

// ================= K2: H = bf16(tanh(he + hd + b1)), computed ONCE ============
// one CTA per bm row (1024 CTAs): 128 n-rows x 512 k
__global__ __launch_bounds__(256) void tanh_k(const float* __restrict__ b1){
    __shared__ float sHE[512];
    const int bm = blockIdx.x;          // 0..1023
    const int b  = bm >> 8;
    const int t  = threadIdx.x;
    if (t < 128){
        float4 h  = ((const float4*)(g_he + bm*Ddim))[t];
        float4 bb = ((const float4*)b1)[t];
        float4 v; v.x=h.x+bb.x; v.y=h.y+bb.y; v.z=h.z+bb.z; v.w=h.w+bb.w;
        ((float4*)sHE)[t] = v;
    }
    __syncthreads();
    const float* hdB = g_hd + ((size_t)b << 16);
    __nv_bfloat16* Hb = g_H + ((size_t)bm << 16);   // bm*128*512
#pragma unroll 4
    for (int i = t; i < 128*64; i += 256){
        const int n = i >> 6;
        const int k = (i & 63) << 3;
        float4 d0 = *(const float4*)(hdB + n*Ddim + k);
        float4 d1 = *(const float4*)(hdB + n*Ddim + k + 4);
        float4 h0 = *(const float4*)(sHE + k);
        float4 h1 = *(const float4*)(sHE + k + 4);
        uint4 o;
        o.x = pk(tanh_fast(h0.x + d0.x), tanh_fast(h0.y + d0.y));
        o.y = pk(tanh_fast(h0.z + d0.z), tanh_fast(h0.w + d0.w));
        o.z = pk(tanh_fast(h1.x + d1.x), tanh_fast(h1.y + d1.y));
        o.w = pk(tanh_fast(h1.z + d1.z), tanh_fast(h1.w + d1.w));
        *(uint4*)(Hb + n*Ddim + k) = o;
    }
}

// ================= K3: bf16 GEMM C = H x w2^T, fused epilogue ==================
// CTA 256 rows x 128 cols, 512 threads, 16 warps 4(m)x4(n), warp tile 64x32.
// smem: 2 stages x (A 256x80B + B 128x80B) = 61440 B
#define PITCH 80
#define STAGE 30720
#define BOFF  20480

__global__ __launch_bounds__(512,1) void gemm_k(const float* __restrict__ b2,
                                                float* __restrict__ out){
    extern __shared__ __align__(128) char smem[];
    const int t   = threadIdx.x;
    const int w   = t >> 5, l = t & 31;
    const int wm  = w >> 2, wn = w & 3;
    const int lq  = l >> 2, lr = l & 3;
    const int bid = blockIdx.x;
    const int rt  = bid >> 3, ci = bid & 7;
    const int g0  = rt << 8;
    const int cb  = ci << 7;

    const int pr  = t >> 2;          // 0..127
    const int sc4 = t & 3;           // 16B slot within 64B row

    const __nv_bfloat16* A0 = g_H   + (size_t)(g0 + pr)*Ddim + (sc4 << 3);
    const __nv_bfloat16* A1 = A0    + (size_t)128*Ddim;
    const __nv_bfloat16* Bp = g_w2b + (size_t)(cb + pr)*Ddim + (sc4 << 3);

    char* sAst = smem + pr*PITCH + (sc4 << 4);
    char* sBst = smem + BOFF + pr*PITCH + (sc4 << 4);

    float acc[4][4][4];
#pragma unroll
    for (int mt = 0; mt < 4; mt++)
#pragma unroll
        for (int nt = 0; nt < 4; nt++)
#pragma unroll
            for (int i = 0; i < 4; i++) acc[mt][nt][i] = 0.f;

    // chunk 0 -> stage 0
    uint4 a0 = *(const uint4*)A0;
    uint4 a1 = *(const uint4*)A1;
    uint4 bv = *(const uint4*)Bp;
    *(uint4*)sAst = a0;
    *(uint4*)(sAst + 128*PITCH) = a1;
    *(uint4*)sBst = bv;
    // prefetch chunk 1
    a0 = *(const uint4*)(A0 + 32);
    a1 = *(const uint4*)(A1 + 32);
    bv = *(const uint4*)(Bp + 32);
    __syncthreads();

    int buf = 0;
#pragma unroll 1
    for (int kc = 0; kc < 16; kc++){
        const char* A  = smem + buf*STAGE;
        const char* Bm = A + BOFF;
#pragma unroll
        for (int s = 0; s < 2; s++){
            const int off = (s << 5) + (lr << 2);
            unsigned af[4][4], bf[4][2];
#pragma unroll
            for (int mt = 0; mt < 4; mt++){
                const char* ap = A + ((wm << 6) + (mt << 4) + lq)*PITCH + off;
                af[mt][0] = *(const unsigned*)ap;
                af[mt][1] = *(const unsigned*)(ap + 8*PITCH);
                af[mt][2] = *(const unsigned*)(ap + 16);
                af[mt][3] = *(const unsigned*)(ap + 8*PITCH + 16);
            }
#pragma unroll
            for (int nt = 0; nt < 4; nt++){
                const char* bp = Bm + ((wn << 5) + (nt << 3) + lq)*PITCH + off;
                bf[nt][0] = *(const unsigned*)bp;
                bf[nt][1] = *(const unsigned*)(bp + 16);
            }
#pragma unroll
            for (int mt = 0; mt < 4; mt++)
#pragma unroll
                for (int nt = 0; nt < 4; nt++)
                    mma_bf16(acc[mt][nt], af[mt], bf[nt]);
        }
        if (kc < 15){
            char* dA = smem + (buf ^ 1)*STAGE + pr*PITCH + (sc4 << 4);
            *(uint4*)dA = a0;
            *(uint4*)(dA + 128*PITCH) = a1;
            *(uint4*)(dA + (BOFF - pr*PITCH - (sc4 << 4)) + pr*PITCH + (sc4 << 4)) = bv;
            if (kc < 14){
                const int ko = (kc + 2) << 5;
                a0 = *(const uint4*)(A0 + ko);
                a1 = *(const uint4*)(A1 + ko);
                bv = *(const uint4*)(Bp + ko);
            }
        }
        __syncthreads();
        buf ^= 1;
    }

    // ---- epilogue: +b2, store logits, per-row (max, sumexp) over 32 cols ----
#pragma unroll
    for (int mt = 0; mt < 4; mt++){
#pragma unroll
        for (int h = 0; h < 2; h++){
            const int r = (wm << 6) + (mt << 4) + lq + (h << 3);
            const int g = g0 + r;
            float v[8];
            float mx = -3.4e38f;
#pragma unroll
            for (int nt = 0; nt < 4; nt++){
                const int c = cb + (wn << 5) + (nt << 3) + (lr << 1);
                float x0 = acc[mt][nt][h*2 + 0] + __ldg(b2 + c);
                float x1 = acc[mt][nt][h*2 + 1] + __ldg(b2 + c + 1);
                v[2*nt] = x0; v[2*nt + 1] = x1;
                mx = fmaxf(mx, fmaxf(x0, x1));
                float2 st; st.x = x0; st.y = x1;
                *(float2*)(out + (size_t)g*Cdim + c) = st;
            }
            mx = fmaxf(mx, __shfl_xor_sync(0xffffffffu, mx, 1));
            mx = fmaxf(mx, __shfl_xor_sync(0xffffffffu, mx, 2));
            float s = 0.f;
#pragma unroll
            for (int i = 0; i < 8; i++) s += __expf(v[i] - mx);
            s += __shfl_xor_sync(0xffffffffu, s, 1);
            s += __shfl_xor_sync(0xffffffffu, s, 2);
            if (lr == 0){
                float2 p; p.x = mx; p.y = s;
                *(float2*)(g_part + (size_t)g*64 + (((ci << 2) + wn) << 1)) = p;
            }
        }
    }
}

// ================= K4: combine 32 partials/row -> lse =================
__global__ __launch_bounds__(256) void lse_k(){
    const int g = blockIdx.x*256 + threadIdx.x;
    const float* p = g_part + (size_t)g*64;
    float mx = -3.4e38f;
#pragma unroll
    for (int i = 0; i < 32; i++) mx = fmaxf(mx, p[2*i]);
    float s = 0.f;
#pragma unroll
    for (int i = 0; i < 32; i++) s += p[2*i + 1]*__expf(p[2*i] - mx);
    g_lse[g] = mx + __logf(s);
}

// ================= K5: out[row, c] -= lse[row] =================
__global__ __launch_bounds__(256) void sub_k(float* __restrict__ out){
    const size_t i = (size_t)blockIdx.x*256 + threadIdx.x;   // float4 index
    const float l = __ldg(g_lse + (i >> 8));
    float4 v = ((const float4*)out)[i];
    v.x -= l; v.y -= l; v.z -= l; v.w -= l;
    ((float4*)out)[i] = v;
}

// ================= launch =================
extern "C" void kernel_launch(void* const* d_in, const int* in_sizes, int n_in,
                              void* d_out, int out_size){
    (void)in_sizes; (void)n_in; (void)out_size;
    const float* enc = (const float*)d_in[0];
    const float* dec = (const float*)d_in[1];
    const float* w1  = (const float*)d_in[2];
    const float* b1  = (const float*)d_in[3];
    const float* w2  = (const float*)d_in[4];
    const float* b2  = (const float*)d_in[5];
    float* out = (float*)d_out;

    cudaFuncSetAttribute(gemm_k, cudaFuncAttributeMaxDynamicSharedMemorySize, 65536);

    cvtw2b_k<<<(Cdim*Ddim/8)/256, 256>>>(w2);
    fc1_k<<<dim3(8, 16), 256>>>(enc, w1, 0,    0);   // he
    fc1_k<<<dim3(8, 8),  256>>>(dec, w1, Ddim, 1);   // hd
    tanh_k<<<Bdim*Mdim, 256>>>(b1);
    gemm_k<<<4096, 512, 2*STAGE>>>(b2, out);
    lse_k<<<ROWS/256, 256>>>();
    sub_k<<<(ROWS*(Cdim/4))/256, 256>>>(out);
}